// round 4
// baseline (speedup 1.0000x reference)
#include <cuda_runtime.h>

#define L_LAYERS 6
#define DIMV     40
#define HV       128
#define ADIMV    20
#define BTOT     131072
#define MTILE    128
#define NTHR     256
#define HSTR     132     // h row stride: 132 % 32 == 4 -> conflict-free frag LDS
#define ZASTR    28

// packed tf32 weight buffer offsets (floats, per layer)
#define PK_A   0          // W1 rows 0..19(+4 pad), KS=3,  NTP=8 (float4 blocks)
#define PK_C   3072       // W1 rows 20..147
#define PK_T   19456      // W1 rows 148..275
#define PK_W2  35840
#define PK_W3  52224
#define PK_W4  68608      // [Ws|Wt|0pad], KS=16, NT=6 (float2 blocks)
#define PK_L   74752

#define SMEM_FLOATS (MTILE*HSTR + MTILE*ZASTR + MTILE*ADIMV + 4*ADIMV)
#define SMEM_BYTES  (SMEM_FLOATS * 4)

__device__ float g_wp[6 * PK_L];
__device__ float g_apk[2 * (size_t)BTOT * HV];   // ctx|te in tf32 A-frag order

__device__ __forceinline__ unsigned f2tf(float x) {
    unsigned r;
    asm("cvt.rna.tf32.f32 %0, %1;" : "=r"(r) : "f"(x));
    return r;
}

__device__ __forceinline__ void mma8(float c[4], const unsigned a[4], const unsigned b[2]) {
    asm volatile(
        "mma.sync.aligned.m16n8k8.row.col.f32.tf32.tf32.f32 "
        "{%0,%1,%2,%3}, {%4,%5,%6,%7}, {%8,%9}, {%0,%1,%2,%3};\n"
        : "+f"(c[0]), "+f"(c[1]), "+f"(c[2]), "+f"(c[3])
        : "r"(a[0]), "r"(a[1]), "r"(a[2]), "r"(a[3]), "r"(b[0]), "r"(b[1]));
}

// ---------------------------------------------------------------------------
// weight prep (unchanged layout from R3)
// ---------------------------------------------------------------------------
__global__ void prep_w_kernel(const float* __restrict__ W1, const float* __restrict__ W2,
                              const float* __restrict__ W3, const float* __restrict__ Ws,
                              const float* __restrict__ Wt) {
    int i = blockIdx.x * blockDim.x + threadIdx.x;
    if (i >= 6 * PK_L) return;
    int layer = i / PK_L;
    int r = i - layer * PK_L;
    float v;
    if (r < PK_W4) {
        int idx, seg;
        if (r < PK_C)      { idx = r;         seg = 0; }
        else if (r < PK_T) { idx = r - PK_C;  seg = 1; }
        else if (r < PK_W2){ idx = r - PK_T;  seg = 2; }
        else if (r < PK_W3){ idx = r - PK_W2; seg = 3; }
        else               { idx = r - PK_W3; seg = 4; }
        int comp = idx & 3, ntl = comp >> 1, hh = comp & 1;
        int lane = (idx >> 2) & 31, t4 = lane & 3, g = lane >> 2;
        int blk = idx >> 7, ntp = blk & 7, ks = blk >> 3;
        int row = ks * 8 + t4 + 4 * hh;
        int col = (ntp * 2 + ntl) * 8 + g;
        if (seg == 0)      v = (row < ADIMV) ? W1[(size_t)layer * 276 * HV + row * HV + col] : 0.0f;
        else if (seg == 1) v = W1[(size_t)layer * 276 * HV + (ADIMV + row) * HV + col];
        else if (seg == 2) v = W1[(size_t)layer * 276 * HV + (ADIMV + 128 + row) * HV + col];
        else if (seg == 3) v = W2[(size_t)layer * HV * HV + row * HV + col];
        else               v = W3[(size_t)layer * HV * HV + row * HV + col];
        g_wp[i] = __uint_as_float(f2tf(v));
    } else {
        int idx = r - PK_W4;
        int hh = idx & 1;
        int lane = (idx >> 1) & 31, t4 = lane & 3, g = lane >> 2;
        int blk = idx >> 6, nt = blk % 6, ks = blk / 6;
        int row = ks * 8 + t4 + 4 * hh;
        int col = nt * 8 + g;
        if (col < ADIMV)     v = Ws[(size_t)layer * HV * ADIMV + row * ADIMV + col];
        else if (col < DIMV) v = Wt[(size_t)layer * HV * ADIMV + row * ADIMV + (col - ADIMV)];
        else                 v = 0.0f;
        g_wp[i] = __uint_as_float(f2tf(v));
    }
}

// ---------------------------------------------------------------------------
// ctx/te prep: tf32-convert and pack into A-fragment order.
// out[((blk16*16+ks)*32+lane)*4+j]; row = blk16*16 + (lane>>2) + 8*(j&1);
// col = ks*8 + (lane&3) + 4*(j>>1)
// ---------------------------------------------------------------------------
__global__ void prep_a_kernel(const float* __restrict__ ctx, const float* __restrict__ te) {
    size_t i = (size_t)blockIdx.x * blockDim.x + threadIdx.x;
    const size_t seg_sz = (size_t)BTOT * HV;
    if (i >= 2 * seg_sz) return;
    int seg = (int)(i / seg_sz);
    size_t idx = i - (size_t)seg * seg_sz;
    int j = (int)(idx & 3);
    int lane = (int)((idx >> 2) & 31);
    int ks = (int)((idx >> 7) & 15);
    size_t blk16 = idx >> 11;
    size_t row = blk16 * 16 + (lane >> 2) + 8 * (j & 1);
    int col = ks * 8 + (lane & 3) + 4 * (j >> 1);
    const float* src = seg ? te : ctx;
    g_apk[i] = __uint_as_float(f2tf(src[row * HV + col]));
}

// ---------------------------------------------------------------------------
// gemm: 4m x 2n warps, warp tile 32x64 (mt=2) over 128x128
// ---------------------------------------------------------------------------
__device__ __forceinline__ void gemm_smemA(float acc[2][8][4], const float* __restrict__ Ab,
                                           const float* __restrict__ Wp,
                                           int wm, int wn, int lane, int g, int t4) {
    const float4* bp = reinterpret_cast<const float4*>(Wp);
#pragma unroll
    for (int ks = 0; ks < 16; ks++) {
        unsigned a[2][4];
#pragma unroll
        for (int mt = 0; mt < 2; mt++) {
            const float* ar = Ab + (wm * 32 + mt * 16 + g) * HSTR + ks * 8 + t4;
            a[mt][0] = __float_as_uint(ar[0]);
            a[mt][1] = __float_as_uint(ar[8 * HSTR]);
            a[mt][2] = __float_as_uint(ar[4]);
            a[mt][3] = __float_as_uint(ar[8 * HSTR + 4]);
        }
        const float4* bb = bp + (ks * 8 + wn * 4) * 32 + lane;
#pragma unroll
        for (int ntp = 0; ntp < 4; ntp++) {
            float4 bv = __ldg(bb + ntp * 32);
            unsigned b0[2] = {__float_as_uint(bv.x), __float_as_uint(bv.y)};
            unsigned b1[2] = {__float_as_uint(bv.z), __float_as_uint(bv.w)};
#pragma unroll
            for (int mt = 0; mt < 2; mt++) {
                mma8(acc[mt][2 * ntp], a[mt], b0);
                mma8(acc[mt][2 * ntp + 1], a[mt], b1);
            }
        }
    }
}

__device__ __forceinline__ void gemm_pkA(float acc[2][8][4], const float* __restrict__ Apk,
                                         const float* __restrict__ Wp, int blkbase,
                                         int wn, int lane) {
    const float4* ap = reinterpret_cast<const float4*>(Apk);
    const float4* bp = reinterpret_cast<const float4*>(Wp);
#pragma unroll
    for (int ks = 0; ks < 16; ks++) {
        float4 af[2];
        af[0] = __ldg(ap + ((size_t)(blkbase) * 16 + ks) * 32 + lane);
        af[1] = __ldg(ap + ((size_t)(blkbase + 1) * 16 + ks) * 32 + lane);
        const float4* bb = bp + (ks * 8 + wn * 4) * 32 + lane;
#pragma unroll
        for (int ntp = 0; ntp < 4; ntp++) {
            float4 bv = __ldg(bb + ntp * 32);
            unsigned b0[2] = {__float_as_uint(bv.x), __float_as_uint(bv.y)};
            unsigned b1[2] = {__float_as_uint(bv.z), __float_as_uint(bv.w)};
#pragma unroll
            for (int mt = 0; mt < 2; mt++) {
                const unsigned* a = reinterpret_cast<const unsigned*>(&af[mt]);
                mma8(acc[mt][2 * ntp], a, b0);
                mma8(acc[mt][2 * ntp + 1], a, b1);
            }
        }
    }
}

__device__ __forceinline__ void epi_silu(float acc[2][8][4], const float* __restrict__ bias,
                                         float* __restrict__ h, int wm, int wn, int g, int t4) {
#pragma unroll
    for (int mt = 0; mt < 2; mt++)
#pragma unroll
        for (int nt = 0; nt < 8; nt++)
#pragma unroll
            for (int e = 0; e < 4; e++) {
                int row = wm * 32 + mt * 16 + g + ((e >= 2) ? 8 : 0);
                int col = wn * 64 + nt * 8 + t4 * 2 + (e & 1);
                float v = acc[mt][nt][e] + __ldg(bias + col);
                v = __fdividef(v, 1.0f + __expf(-v));
                h[row * HSTR + col] = __uint_as_float(f2tf(v));
            }
}

__device__ __forceinline__ void zacc(float acc[2][8][4]) {
#pragma unroll
    for (int mt = 0; mt < 2; mt++)
#pragma unroll
        for (int nt = 0; nt < 8; nt++)
#pragma unroll
            for (int e = 0; e < 4; e++) acc[mt][nt][e] = 0.0f;
}

// ---------------------------------------------------------------------------
__global__ void __launch_bounds__(NTHR, 2)
flow_fused_kernel(const float* __restrict__ xin, float* __restrict__ zfinal,
                  float* __restrict__ ldfinal,
                  const float* __restrict__ b1, const float* __restrict__ b2,
                  const float* __restrict__ b3, const float* __restrict__ bsw,
                  const float* __restrict__ btw,
                  const int* __restrict__ perm, const int* __restrict__ idxa,
                  const int* __restrict__ idxb) {
    extern __shared__ float sm[];
    float* h_s  = sm;
    float* za_s = h_s + MTILE * HSTR;
    float* zb_s = za_s + MTILE * ZASTR;
    int* sia = (int*)(zb_s + MTILE * ADIMV);
    int* sib = sia + ADIMV;
    int* sga = sib + ADIMV;
    int* sgb = sga + ADIMV;

    const int tid = threadIdx.x;
    const int warp = tid >> 5, lane = tid & 31;
    const int g = lane >> 2, t4 = lane & 3;
    const int wm = warp >> 1, wn = warp & 1;
    const int rb = blockIdx.x * MTILE;
    const int blkbase = (rb >> 4) + wm * 2;   // 16-row block index of warp's A rows

    // initial z = x into h cols 64..103
    for (int i = tid; i < MTILE * DIMV; i += NTHR) {
        int r = i / DIMV, c = i - r * DIMV;
        h_s[r * HSTR + 64 + c] = xin[(size_t)(rb + r) * DIMV + c];
    }

    float ldacc = 0.0f;

    for (int layer = 0; layer < L_LAYERS; layer++) {
        const float* wl = g_wp + layer * PK_L;

        if (tid < ADIMV) {
            int v = idxa[layer * ADIMV + tid];
            sia[tid] = v;
            sga[tid] = perm[layer * DIMV + v];
        } else if (tid < 2 * ADIMV) {
            int k = tid - ADIMV;
            int v = idxb[layer * ADIMV + k];
            sib[k] = v;
            sgb[k] = perm[layer * DIMV + v];
        }
        __syncthreads();
        for (int i = tid; i < MTILE * ADIMV; i += NTHR) {
            int r = i / ADIMV, k = i - r * ADIMV;
            za_s[r * ZASTR + k] = h_s[r * HSTR + 64 + sga[k]];
            zb_s[r * ADIMV + k] = h_s[r * HSTR + 64 + sgb[k]];
        }
        for (int i = tid; i < MTILE * 4; i += NTHR) {
            int r = i >> 2, c = i & 3;
            za_s[r * ZASTR + ADIMV + c] = 0.0f;
        }
        __syncthreads();

        float acc[2][8][4];
        zacc(acc);

        // GEMM1 seg z_a (K=24, cvt at use from za_s)
        {
            const float4* bp = reinterpret_cast<const float4*>(wl + PK_A);
#pragma unroll
            for (int ks = 0; ks < 3; ks++) {
                unsigned a[2][4];
#pragma unroll
                for (int mt = 0; mt < 2; mt++) {
                    const float* ar = za_s + (wm * 32 + mt * 16 + g) * ZASTR + ks * 8 + t4;
                    a[mt][0] = f2tf(ar[0]);
                    a[mt][1] = f2tf(ar[8 * ZASTR]);
                    a[mt][2] = f2tf(ar[4]);
                    a[mt][3] = f2tf(ar[8 * ZASTR + 4]);
                }
                const float4* bb = bp + (ks * 8 + wn * 4) * 32 + lane;
#pragma unroll
                for (int ntp = 0; ntp < 4; ntp++) {
                    float4 bv = __ldg(bb + ntp * 32);
                    unsigned b0[2] = {__float_as_uint(bv.x), __float_as_uint(bv.y)};
                    unsigned b1[2] = {__float_as_uint(bv.z), __float_as_uint(bv.w)};
#pragma unroll
                    for (int mt = 0; mt < 2; mt++) {
                        mma8(acc[mt][2 * ntp], a[mt], b0);
                        mma8(acc[mt][2 * ntp + 1], a[mt], b1);
                    }
                }
            }
        }
        // GEMM1 ctx / te segments from prepacked A (no staging)
        gemm_pkA(acc, g_apk, wl + PK_C, blkbase, wn, lane);
        gemm_pkA(acc, g_apk + (size_t)BTOT * HV, wl + PK_T, blkbase, wn, lane);
        epi_silu(acc, b1 + layer * HV, h_s, wm, wn, g, t4);
        __syncthreads();

        // GEMM2
        zacc(acc);
        gemm_smemA(acc, h_s, wl + PK_W2, wm, wn, lane, g, t4);
        __syncthreads();
        epi_silu(acc, b2 + layer * HV, h_s, wm, wn, g, t4);
        __syncthreads();

        // GEMM3
        zacc(acc);
        gemm_smemA(acc, h_s, wl + PK_W3, wm, wn, lane, g, t4);
        __syncthreads();
        epi_silu(acc, b3 + layer * HV, h_s, wm, wn, g, t4);
        __syncthreads();

        // GEMM4: h @ [Ws|Wt] (N=48), warp tile 32x24
        float a4[2][3][4];
#pragma unroll
        for (int mt = 0; mt < 2; mt++)
#pragma unroll
            for (int nt = 0; nt < 3; nt++)
#pragma unroll
                for (int e = 0; e < 4; e++) a4[mt][nt][e] = 0.0f;
        {
            const float2* bp2 = reinterpret_cast<const float2*>(wl + PK_W4);
#pragma unroll
            for (int ks = 0; ks < 16; ks++) {
                unsigned a[2][4];
#pragma unroll
                for (int mt = 0; mt < 2; mt++) {
                    const float* ar = h_s + (wm * 32 + mt * 16 + g) * HSTR + ks * 8 + t4;
                    a[mt][0] = __float_as_uint(ar[0]);
                    a[mt][1] = __float_as_uint(ar[8 * HSTR]);
                    a[mt][2] = __float_as_uint(ar[4]);
                    a[mt][3] = __float_as_uint(ar[8 * HSTR + 4]);
                }
#pragma unroll
                for (int nt = 0; nt < 3; nt++) {
                    float2 bv = __ldg(bp2 + (ks * 6 + wn * 3 + nt) * 32 + lane);
                    unsigned b[2] = {__float_as_uint(bv.x), __float_as_uint(bv.y)};
                    mma8(a4[0][nt], a[0], b);
                    mma8(a4[1][nt], a[1], b);
                }
            }
        }
        __syncthreads();
        // epilogue4 -> h cols 0..39 (s clipped | t)
        {
            const float* bsl = bsw + layer * ADIMV;
            const float* btl = btw + layer * ADIMV;
#pragma unroll
            for (int mt = 0; mt < 2; mt++)
#pragma unroll
                for (int nt = 0; nt < 3; nt++)
#pragma unroll
                    for (int e = 0; e < 4; e++) {
                        int row = wm * 32 + mt * 16 + g + ((e >= 2) ? 8 : 0);
                        int col = wn * 24 + nt * 8 + t4 * 2 + (e & 1);
                        if (col < DIMV) {
                            float v = a4[mt][nt][e];
                            if (col < ADIMV) {
                                v += __ldg(bsl + col);
                                v = fminf(fmaxf(v, -2.0f), 2.0f);
                            } else {
                                v += __ldg(btl + col - ADIMV);
                            }
                            h_s[row * HSTR + col] = v;
                        }
                    }
        }
        __syncthreads();

        // coupling: 2 threads/row; write new z into h cols 64..103
        {
            int r = tid >> 1, q = tid & 1;
            float ssum = 0.0f;
#pragma unroll
            for (int j = 0; j < 10; j++) {
                int k = q * 10 + j;
                float s = h_s[r * HSTR + k];
                float t = h_s[r * HSTR + ADIMV + k];
                ssum += s;
                float yb = zb_s[r * ADIMV + k] * __expf(s) + t;
                h_s[r * HSTR + 64 + sib[k]] = yb;
                h_s[r * HSTR + 64 + sia[k]] = za_s[r * ZASTR + k];
            }
            ssum += __shfl_xor_sync(0xffffffffu, ssum, 1);
            ldacc += ssum;
        }
        __syncthreads();
    }

    // final writeback
    for (int i = tid; i < MTILE * DIMV; i += NTHR) {
        int r = i / DIMV, c = i - r * DIMV;
        zfinal[(size_t)(rb + r) * DIMV + c] = h_s[r * HSTR + 64 + c];
    }
    if ((tid & 1) == 0) {
        int r = tid >> 1;
        ldfinal[(size_t)rb + r] = ldacc;
    }
}

extern "C" void kernel_launch(void* const* d_in, const int* in_sizes, int n_in,
                              void* d_out, int out_size) {
    const float* x   = (const float*)d_in[0];
    const float* ctx = (const float*)d_in[1];
    const float* te  = (const float*)d_in[2];
    const float* W1  = (const float*)d_in[3];
    const float* b1  = (const float*)d_in[4];
    const float* W2  = (const float*)d_in[5];
    const float* b2  = (const float*)d_in[6];
    const float* W3  = (const float*)d_in[7];
    const float* b3  = (const float*)d_in[8];
    const float* Ws  = (const float*)d_in[9];
    const float* bs  = (const float*)d_in[10];
    const float* Wt  = (const float*)d_in[11];
    const float* bt  = (const float*)d_in[12];
    const int* perm  = (const int*)d_in[13];
    const int* ia    = (const int*)d_in[14];
    const int* ib    = (const int*)d_in[15];

    float* outz  = (float*)d_out;
    float* outld = outz + (size_t)BTOT * DIMV;

    prep_w_kernel<<<(6 * PK_L + 255) / 256, 256>>>(W1, W2, W3, Ws, Wt);
    {
        size_t tot = 2 * (size_t)BTOT * HV;
        prep_a_kernel<<<(unsigned)((tot + 255) / 256), 256>>>(ctx, te);
    }

    cudaFuncSetAttribute(flow_fused_kernel,
                         cudaFuncAttributeMaxDynamicSharedMemorySize, SMEM_BYTES);
    dim3 grid(BTOT / MTILE), blk(NTHR);
    flow_fused_kernel<<<grid, blk, SMEM_BYTES>>>(
        x, outz, outld, b1, b2, b3, bs, bt, perm, ia, ib);
    (void)in_sizes; (void)n_in; (void)out_size;
}